// round 4
// baseline (speedup 1.0000x reference)
#include <cuda_runtime.h>

// ---------------------------------------------------------------------------
// SAGEConv (cugraph, mean agg, concat root):
//   edge-dtype auto-detect (int32 vs int64, device-side) ->
//   CSC build (int atomics only) -> gather-aggregate (no float atomics) ->
//   fused concat GEMM + bias.
// ---------------------------------------------------------------------------

#define N_MAX 100000
#define E_MAX 1600000
#define F 64
#define KDIM 128
#define SCAN_B 1024
#define SCAN_BLOCKS_MAX 128   // ceil(100000/1024)=98

// Scratch (__device__ globals per allocation-free rule)
__device__ __align__(16) float g_agg[N_MAX * F];   // mean-aggregated features
__device__ int g_cnt[N_MAX];        // in-degree
__device__ int g_rowptr[N_MAX];     // CSC start offsets
__device__ int g_cursor[N_MAX];     // fill cursors
__device__ int g_ebuf[E_MAX];       // src ids grouped by dst
__device__ int g_bsum[SCAN_BLOCKS_MAX];
__device__ int g_is64;              // 1 if edge_index stored as int64

// --------------------------------------------------------------------------
// Edge accessors. ei = edge buffer viewed as int32 words, E = #edges.
//  int64 layout: src[e] at word 2e (hi word 0), dst[e] at word 2E+2e.
//  int32 layout: src[e] at word e,              dst[e] at word E+e.
__device__ __forceinline__ int edge_src(const int* ei, int is64, int E, int e, int N) {
    int v = is64 ? ei[2 * e] : ei[e];
    return min(max(v, 0), N - 1);
}
__device__ __forceinline__ int edge_dst(const int* ei, int is64, int E, int e, int N) {
    int v = is64 ? ei[2 * E + 2 * e] : ei[E + e];
    return min(max(v, 0), N - 1);
}

// Detect dtype: for int64 (values < 2^31, non-negative) every hi word is 0.
__global__ void detect_kernel(const int* __restrict__ ei, int E) {
    __shared__ int bad;
    if (threadIdx.x == 0) bad = 0;
    __syncthreads();
    int n = min(E, 2048);          // 2*n words touched, < 2*E words always
    for (int i = threadIdx.x; i < n; i += blockDim.x)
        if (ei[2 * i + 1] != 0) bad = 1;   // benign race
    __syncthreads();
    if (threadIdx.x == 0) g_is64 = bad ? 0 : 1;
}

__global__ void zero_cnt_kernel(int N) {
    int i = blockIdx.x * blockDim.x + threadIdx.x;
    if (i < N) g_cnt[i] = 0;
}

// 1 thread / edge: histogram of destinations (int REDG)
__global__ void hist_kernel(const int* __restrict__ ei, int E, int N) {
    int e = blockIdx.x * blockDim.x + threadIdx.x;
    if (e < E) {
        int is64 = g_is64;
        atomicAdd(&g_cnt[edge_dst(ei, is64, E, e, N)], 1);
    }
}

// per-block sums of cnt
__global__ __launch_bounds__(SCAN_B)
void scan1_kernel(int N) {
    __shared__ int sh[SCAN_B];
    int i = blockIdx.x * SCAN_B + threadIdx.x;
    sh[threadIdx.x] = (i < N) ? g_cnt[i] : 0;
    __syncthreads();
    for (int off = SCAN_B / 2; off > 0; off >>= 1) {
        if (threadIdx.x < off) sh[threadIdx.x] += sh[threadIdx.x + off];
        __syncthreads();
    }
    if (threadIdx.x == 0) g_bsum[blockIdx.x] = sh[0];
}

// serial exclusive scan of the (<=128) block sums
__global__ void scan2_kernel(int nblocks) {
    if (threadIdx.x == 0 && blockIdx.x == 0) {
        int run = 0;
        for (int b = 0; b < nblocks; b++) {
            int t = g_bsum[b];
            g_bsum[b] = run;
            run += t;
        }
    }
}

// per-block exclusive rescan + base -> rowptr & cursor
__global__ __launch_bounds__(SCAN_B)
void scan3_kernel(int N) {
    __shared__ int sh[SCAN_B];
    int tid = threadIdx.x;
    int i = blockIdx.x * SCAN_B + tid;
    int v = (i < N) ? g_cnt[i] : 0;
    sh[tid] = v;
    __syncthreads();
    for (int off = 1; off < SCAN_B; off <<= 1) {
        int t = (tid >= off) ? sh[tid - off] : 0;
        __syncthreads();
        sh[tid] += t;
        __syncthreads();
    }
    if (i < N) {
        int start = g_bsum[blockIdx.x] + sh[tid] - v;  // exclusive
        g_rowptr[i] = start;
        g_cursor[i] = start;
    }
}

// bucket fill: ebuf[dst-grouped] = src
__global__ void fill_kernel(const int* __restrict__ ei, int E, int N) {
    int e = blockIdx.x * blockDim.x + threadIdx.x;
    if (e < E) {
        int is64 = g_is64;
        int d = edge_dst(ei, is64, E, e, N);
        int pos = atomicAdd(&g_cursor[d], 1);
        if (pos >= 0 && pos < E_MAX)
            g_ebuf[pos] = edge_src(ei, is64, E, e, N);
    }
}

// gather-aggregate: 1 warp / node, lane owns 2 features (float2).
__global__ __launch_bounds__(256)
void agg_kernel(const float2* __restrict__ x2, int N) {
    int warp = (blockIdx.x * blockDim.x + threadIdx.x) >> 5;
    int lane = threadIdx.x & 31;
    if (warp >= N) return;

    int start = g_rowptr[warp];
    int deg   = g_cnt[warp];

    float2 acc = make_float2(0.f, 0.f);
    for (int j = 0; j < deg; j++) {
        int s = g_ebuf[start + j];           // same addr all lanes -> broadcast
        float2 v = __ldg(x2 + (size_t)s * 32 + lane);
        acc.x += v.x; acc.y += v.y;
    }
    float inv = 1.0f / (float)max(deg, 1);
    acc.x *= inv; acc.y *= inv;
    ((float2*)g_agg)[(size_t)warp * 32 + lane] = acc;
}

// --------------------------------------------------------------------------
// Fused concat GEMM + bias. 64 nodes x 64 cols / block, 4x4 micro-tiles.
__global__ __launch_bounds__(256)
void gemm_kernel(const float* __restrict__ x,
                 const float* __restrict__ W,      // [64][128]
                 const float* __restrict__ bias,   // [64]
                 float* __restrict__ out, int N) {
    __shared__ float As[64][65];
    __shared__ float Ws[64][65];

    int tid = threadIdx.x;
    int tx = tid & 15;
    int ty = tid >> 4;
    int n0 = blockIdx.x * 64;

    float acc[4][4] = {};

    for (int kt = 0; kt < 2; kt++) {
        for (int i = tid; i < 64 * 64; i += 256) {
            int o = i >> 6, k = i & 63;
            Ws[k][o] = W[o * KDIM + kt * 64 + k];
        }
        const float* srcA = (kt == 0) ? g_agg : x;
        for (int i = tid; i < 64 * 16; i += 256) {
            int row = i >> 4, c4 = i & 15;
            int n = n0 + row;
            float4 v = make_float4(0.f, 0.f, 0.f, 0.f);
            if (n < N) v = __ldg(((const float4*)srcA) + (size_t)n * 16 + c4);
            As[row][c4 * 4 + 0] = v.x;
            As[row][c4 * 4 + 1] = v.y;
            As[row][c4 * 4 + 2] = v.z;
            As[row][c4 * 4 + 3] = v.w;
        }
        __syncthreads();

        #pragma unroll 4
        for (int k = 0; k < 64; k++) {
            float a[4], w[4];
            #pragma unroll
            for (int i2 = 0; i2 < 4; i2++) a[i2] = As[ty * 4 + i2][k];
            #pragma unroll
            for (int j = 0; j < 4; j++)  w[j] = Ws[k][tx * 4 + j];
            #pragma unroll
            for (int i2 = 0; i2 < 4; i2++)
                #pragma unroll
                for (int j = 0; j < 4; j++)
                    acc[i2][j] = fmaf(a[i2], w[j], acc[i2][j]);
        }
        __syncthreads();
    }

    float b0 = bias[tx * 4 + 0], b1 = bias[tx * 4 + 1];
    float b2 = bias[tx * 4 + 2], b3 = bias[tx * 4 + 3];
    #pragma unroll
    for (int i2 = 0; i2 < 4; i2++) {
        int n = n0 + ty * 4 + i2;
        if (n < N) {
            float4 o4;
            o4.x = acc[i2][0] + b0;
            o4.y = acc[i2][1] + b1;
            o4.z = acc[i2][2] + b2;
            o4.w = acc[i2][3] + b3;
            ((float4*)out)[(size_t)n * 16 + tx] = o4;
        }
    }
}

// --------------------------------------------------------------------------
// Size-based input binding: b=64, W=8192, scalar<=2, larger big array = x,
// smaller big array = edge_index (element count 2E for either dtype).
extern "C" void kernel_launch(void* const* d_in, const int* in_sizes, int n_in,
                              void* d_out, int out_size) {
    const float* x  = nullptr;
    const int*   ei = nullptr;
    const float* W  = nullptr;
    const float* b  = nullptr;
    int xsz = 0, esz = 0;

    for (int i = 0; i < n_in; i++) {
        int sz = in_sizes[i];
        if (sz == 64) b = (const float*)d_in[i];
        else if (sz == 8192) W = (const float*)d_in[i];
        else if (sz <= 2) { /* num_nodes scalar */ }
        else {
            if (sz > xsz) {
                if (x) { ei = (const int*)x; esz = xsz; }
                x = (const float*)d_in[i]; xsz = sz;
            } else { ei = (const int*)d_in[i]; esz = sz; }
        }
    }
    if (!x  && n_in > 0) { x  = (const float*)d_in[0]; xsz = in_sizes[0]; }
    if (!ei && n_in > 1) { ei = (const int*)d_in[1];   esz = in_sizes[1]; }
    if (!W  && n_in > 3) W = (const float*)d_in[n_in - 2];
    if (!b  && n_in > 4) b = (const float*)d_in[n_in - 1];

    float* out = (float*)d_out;
    int N = xsz / F;
    int E = esz / 2;        // element count 2E for both int32 and int64
    if (N > N_MAX) N = N_MAX;
    if (E > E_MAX) E = E_MAX;

    int nblocks_scan = (N + SCAN_B - 1) / SCAN_B;

    detect_kernel<<<1, 256>>>(ei, E);
    zero_cnt_kernel<<<(N + 255) / 256, 256>>>(N);
    hist_kernel<<<(E + 255) / 256, 256>>>(ei, E, N);
    scan1_kernel<<<nblocks_scan, SCAN_B>>>(N);
    scan2_kernel<<<1, 32>>>(nblocks_scan);
    scan3_kernel<<<nblocks_scan, SCAN_B>>>(N);
    fill_kernel<<<(E + 255) / 256, 256>>>(ei, E, N);
    agg_kernel<<<(N * 32 + 255) / 256, 256>>>((const float2*)x, N);
    gemm_kernel<<<(N + 63) / 64, 256>>>(x, W, b, out, N);
}

// round 6
// speedup vs baseline: 1.0494x; 1.0494x over previous
#include <cuda_runtime.h>

// ---------------------------------------------------------------------------
// SAGEConv (cugraph, mean agg, concat root):
//   edge-dtype auto-detect -> CSC build (int atomics only) ->
//   FUSED gather-aggregate + concat GEMM (packed f32x2 FFMA) + bias.
// ---------------------------------------------------------------------------

#define N_MAX 100000
#define E_MAX 1600000
#define F 64
#define KDIM 128
#define SCAN_B 1024
#define SCAN_BLOCKS_MAX 128
#define APAD 68   // tile row stride (multiple of 4 floats -> every row 16B-aligned)

// Scratch (__device__ globals per allocation-free rule)
__device__ int g_cnt[N_MAX];
__device__ int g_rowptr[N_MAX];
__device__ int g_cursor[N_MAX];
__device__ int g_ebuf[E_MAX];
__device__ int g_bsum[SCAN_BLOCKS_MAX];
__device__ int g_is64;

// --------------------------------------------------------------------------
__device__ __forceinline__ int edge_src(const int* ei, int is64, int E, int e, int N) {
    int v = is64 ? ei[2 * e] : ei[e];
    return min(max(v, 0), N - 1);
}
__device__ __forceinline__ int edge_dst(const int* ei, int is64, int E, int e, int N) {
    int v = is64 ? ei[2 * E + 2 * e] : ei[E + e];
    return min(max(v, 0), N - 1);
}

// packed f32x2 helpers (Blackwell sm_10x)
__device__ __forceinline__ unsigned long long ffma2(unsigned long long a,
                                                    unsigned long long b,
                                                    unsigned long long c) {
    unsigned long long d;
    asm("fma.rn.f32x2 %0, %1, %2, %3;" : "=l"(d) : "l"(a), "l"(b), "l"(c));
    return d;
}
__device__ __forceinline__ unsigned long long dup2(float w) {
    unsigned long long r;
    asm("mov.b64 %0, {%1, %1};" : "=l"(r) : "f"(w));
    return r;
}
__device__ __forceinline__ float2 unpack2(unsigned long long v) {
    float2 r;
    asm("mov.b64 {%0, %1}, %2;" : "=f"(r.x), "=f"(r.y) : "l"(v));
    return r;
}

// --------------------------------------------------------------------------
// zero cnt + edge dtype detect in one launch
__global__ void prep_kernel(const int* __restrict__ ei, int E, int N) {
    int i = blockIdx.x * blockDim.x + threadIdx.x;
    if (i < N) g_cnt[i] = 0;
    if (blockIdx.x == 0) {
        int ok = 1;
        int n = min(E, 2048);
        for (int j = threadIdx.x; j < n; j += blockDim.x)
            if (ei[2 * j + 1] != 0) ok = 0;    // hi word nonzero -> int32 data
        int all_ok = __syncthreads_and(ok);
        if (threadIdx.x == 0) g_is64 = all_ok ? 1 : 0;
    }
}

__global__ void hist_kernel(const int* __restrict__ ei, int E, int N) {
    int e = blockIdx.x * blockDim.x + threadIdx.x;
    if (e < E) {
        int is64 = g_is64;
        atomicAdd(&g_cnt[edge_dst(ei, is64, E, e, N)], 1);
    }
}

// per-block sums (shuffle reduce)
__global__ __launch_bounds__(SCAN_B)
void scan1_kernel(int N) {
    int i = blockIdx.x * SCAN_B + threadIdx.x;
    int v = (i < N) ? g_cnt[i] : 0;
    #pragma unroll
    for (int o = 16; o > 0; o >>= 1) v += __shfl_down_sync(0xffffffffu, v, o);
    __shared__ int ws[32];
    if ((threadIdx.x & 31) == 0) ws[threadIdx.x >> 5] = v;
    __syncthreads();
    if (threadIdx.x < 32) {
        int t = ws[threadIdx.x];
        #pragma unroll
        for (int o = 16; o > 0; o >>= 1) t += __shfl_down_sync(0xffffffffu, t, o);
        if (threadIdx.x == 0) g_bsum[blockIdx.x] = t;
    }
}

// serial exclusive scan of <=128 block sums
__global__ void scan2_kernel(int nblocks) {
    if (threadIdx.x == 0 && blockIdx.x == 0) {
        int run = 0;
        for (int b = 0; b < nblocks; b++) { int t = g_bsum[b]; g_bsum[b] = run; run += t; }
    }
}

// per-block exclusive rescan (warp shuffles, 2 syncs) -> rowptr & cursor
__global__ __launch_bounds__(SCAN_B)
void scan3_kernel(int N) {
    int tid = threadIdx.x, lane = tid & 31, wid = tid >> 5;
    int i = blockIdx.x * SCAN_B + tid;
    int v = (i < N) ? g_cnt[i] : 0;
    int s = v;
    #pragma unroll
    for (int o = 1; o < 32; o <<= 1) {
        int t = __shfl_up_sync(0xffffffffu, s, o);
        if (lane >= o) s += t;
    }
    __shared__ int wsum[32];
    if (lane == 31) wsum[wid] = s;
    __syncthreads();
    if (tid < 32) {
        int t = wsum[tid];
        int ss = t;
        #pragma unroll
        for (int o = 1; o < 32; o <<= 1) {
            int u = __shfl_up_sync(0xffffffffu, ss, o);
            if (tid >= o) ss += u;
        }
        wsum[tid] = ss - t;   // exclusive
    }
    __syncthreads();
    if (i < N) {
        int start = g_bsum[blockIdx.x] + wsum[wid] + s - v;
        g_rowptr[i] = start;
        g_cursor[i] = start;
    }
}

__global__ void fill_kernel(const int* __restrict__ ei, int E, int N) {
    int e = blockIdx.x * blockDim.x + threadIdx.x;
    if (e < E) {
        int is64 = g_is64;
        int d = edge_dst(ei, is64, E, e, N);
        int pos = atomicAdd(&g_cursor[d], 1);
        if (pos >= 0 && pos < E_MAX)
            g_ebuf[pos] = edge_src(ei, is64, E, e, N);
    }
}

// --------------------------------------------------------------------------
// Inner 64x64x64 MMA step: packed f32x2, node-pairs in 64-bit accumulators.
// As: [k][node], Ws: [k][o] — both stride APAD (16B-aligned rows for LDS.128).
__device__ __forceinline__ void mma_tile(const float (*As)[APAD], const float (*Ws)[APAD],
                                         unsigned long long acc[2][4], int tx, int ty) {
    #pragma unroll 8
    for (int k = 0; k < 64; k++) {
        float4 a4 = *(const float4*)&As[k][ty * 4];   // 4 node values, reg-paired
        float4 w4 = *(const float4*)&Ws[k][tx * 4];
        unsigned long long a01, a23;
        asm("mov.b64 %0, {%1, %2};" : "=l"(a01) : "f"(a4.x), "f"(a4.y));
        asm("mov.b64 %0, {%1, %2};" : "=l"(a23) : "f"(a4.z), "f"(a4.w));
        float wj[4] = {w4.x, w4.y, w4.z, w4.w};
        #pragma unroll
        for (int j = 0; j < 4; j++) {
            unsigned long long wd = dup2(wj[j]);
            acc[0][j] = ffma2(a01, wd, acc[0][j]);
            acc[1][j] = ffma2(a23, wd, acc[1][j]);
        }
    }
}

// Fused: gather-aggregate (mean) -> concat GEMM + bias.
// Block = 256 threads, 64 nodes. Thread (tx,ty): nodes ty*4..+3, cols tx*4..+3.
__global__ __launch_bounds__(256)
void fused_kernel(const float2* __restrict__ x2,
                  const float*  __restrict__ W,      // [64][128]
                  const float*  __restrict__ bias,   // [64]
                  float* __restrict__ out, int N) {
    __shared__ float As[64][APAD];   // [k][node] transposed A tile
    __shared__ float Ws[64][APAD];   // [k][o]

    int tid  = threadIdx.x;
    int lane = tid & 31, warp = tid >> 5;
    int tx = tid & 15, ty = tid >> 4;
    int n0 = blockIdx.x * 64;

    unsigned long long acc[2][4];
    #pragma unroll
    for (int p = 0; p < 2; p++)
        #pragma unroll
        for (int j = 0; j < 4; j++) acc[p][j] = 0ULL;

    // ---- stage Ws (kt=0) ----
    for (int i = tid; i < 64 * 64; i += 256) {
        int o = i >> 6, k = i & 63;
        Ws[k][o] = W[o * KDIM + k];
    }

    // ---- aggregate: 8 nodes per warp, lane owns feature pair (2l, 2l+1) ----
    for (int t = 0; t < 8; t++) {
        int nloc = warp * 8 + t;
        int node = n0 + nloc;
        float2 a = make_float2(0.f, 0.f);
        float inv = 1.f;
        if (node < N) {
            int start = g_rowptr[node];
            int deg   = g_cnt[node];
            for (int base = 0; base < deg; base += 32) {
                int rem = deg - base;
                int cnt = rem < 32 ? rem : 32;
                int myidx = (lane < cnt) ? g_ebuf[start + base + lane] : 0;
                #pragma unroll 4
                for (int j = 0; j < cnt; j++) {
                    int s = __shfl_sync(0xffffffffu, myidx, j);
                    float2 v = __ldg(x2 + (size_t)s * 32 + lane);
                    a.x += v.x; a.y += v.y;
                }
            }
            inv = 1.0f / (float)(deg > 1 ? deg : 1);
        }
        As[2 * lane][nloc]     = a.x * inv;
        As[2 * lane + 1][nloc] = a.y * inv;
    }
    __syncthreads();

    // ---- MMA kt=0 (agg half) ----
    mma_tile(As, Ws, acc, tx, ty);
    __syncthreads();

    // ---- stage Ws (kt=1) + x tile (transposed) ----
    for (int i = tid; i < 64 * 64; i += 256) {
        int o = i >> 6, k = i & 63;
        Ws[k][o] = W[o * KDIM + 64 + k];
    }
    for (int t = 0; t < 8; t++) {
        int nloc = warp * 8 + t;
        int node = n0 + nloc;
        float2 v = make_float2(0.f, 0.f);
        if (node < N) v = __ldg(x2 + (size_t)node * 32 + lane);
        As[2 * lane][nloc]     = v.x;
        As[2 * lane + 1][nloc] = v.y;
    }
    __syncthreads();

    // ---- MMA kt=1 (self half) ----
    mma_tile(As, Ws, acc, tx, ty);

    // ---- epilogue: +bias, float4 stores ----
    float4 bv = *(const float4*)(bias + tx * 4);
    #pragma unroll
    for (int p = 0; p < 2; p++) {
        float2 c0 = unpack2(acc[p][0]);
        float2 c1 = unpack2(acc[p][1]);
        float2 c2 = unpack2(acc[p][2]);
        float2 c3 = unpack2(acc[p][3]);
        int n = n0 + ty * 4 + 2 * p;
        if (n < N) {
            float4 o4 = make_float4(c0.x + bv.x, c1.x + bv.y, c2.x + bv.z, c3.x + bv.w);
            ((float4*)out)[(size_t)n * 16 + tx] = o4;
        }
        if (n + 1 < N) {
            float4 o4 = make_float4(c0.y + bv.x, c1.y + bv.y, c2.y + bv.z, c3.y + bv.w);
            ((float4*)out)[(size_t)(n + 1) * 16 + tx] = o4;
        }
    }
}

// --------------------------------------------------------------------------
extern "C" void kernel_launch(void* const* d_in, const int* in_sizes, int n_in,
                              void* d_out, int out_size) {
    const float* x  = nullptr;
    const int*   ei = nullptr;
    const float* W  = nullptr;
    const float* b  = nullptr;
    int xsz = 0, esz = 0;

    for (int i = 0; i < n_in; i++) {
        int sz = in_sizes[i];
        if (sz == 64) b = (const float*)d_in[i];
        else if (sz == 8192) W = (const float*)d_in[i];
        else if (sz <= 2) { /* num_nodes scalar */ }
        else {
            if (sz > xsz) {
                if (x) { ei = (const int*)x; esz = xsz; }
                x = (const float*)d_in[i]; xsz = sz;
            } else { ei = (const int*)d_in[i]; esz = sz; }
        }
    }
    if (!x  && n_in > 0) { x  = (const float*)d_in[0]; xsz = in_sizes[0]; }
    if (!ei && n_in > 1) { ei = (const int*)d_in[1];   esz = in_sizes[1]; }
    if (!W  && n_in > 3) W = (const float*)d_in[n_in - 2];
    if (!b  && n_in > 4) b = (const float*)d_in[n_in - 1];

    float* out = (float*)d_out;
    int N = xsz / F;
    int E = esz / 2;
    if (N > N_MAX) N = N_MAX;
    if (E > E_MAX) E = E_MAX;

    int nblocks_scan = (N + SCAN_B - 1) / SCAN_B;

    prep_kernel<<<(N + 255) / 256, 256>>>(ei, E, N);
    hist_kernel<<<(E + 255) / 256, 256>>>(ei, E, N);
    scan1_kernel<<<nblocks_scan, SCAN_B>>>(N);
    scan2_kernel<<<1, 32>>>(nblocks_scan);
    scan3_kernel<<<nblocks_scan, SCAN_B>>>(N);
    fill_kernel<<<(E + 255) / 256, 256>>>(ei, E, N);
    fused_kernel<<<(N + 63) / 64, 256>>>((const float2*)x, W, b, out, N);
}